// round 10
// baseline (speedup 1.0000x reference)
#include <cuda_runtime.h>
#include <cstdint>

// SSM scan: h_t = A_t*h_{t-1} + B_t*x_t ; y_t[d] = sum_n C_t[n]*h_t[d,n]
// A,B [2,2048,1024,16] f32; C [2,2048,16]; x [2,2048,1024]; y [2,2048,1024].
//
// R7: replace register-resident LDG prefetch (capped at ~55 outstanding
// requests/warp, ~3.8MB chip-wide in flight, 3.6TB/s) with a TMA
// (cp.async.bulk) -> SMEM ring pipeline. Each block owns 16 d's for one b;
// the per-step A/B slices are contiguous 1KB chunks. 12-stage ring of
// 8-step groups = ~190KB in flight per block x 128 blocks = ~24MB chip-wide.
// Warp-specialized: warp 8 produces (bulk copies + mbarrier), warps 0-7
// consume (LDS + FMA + shfl-reduce + STG).

#define SSM_S 2048
#define SSM_D 1024
#define SSM_N 16
#define SSM_B 2

#define D_PER_BLK 16
#define GRP 8                      // steps per pipeline stage
#define NGRP (SSM_S / GRP)         // 256 groups
#define STAGES 12

#define A_STEP_B 1024              // 16 d * 16 n * 4B
#define X_STEP_B 64                // 16 d * 4B
#define C_STEP_B 64                // 16 n * 4B
#define STAGE_B (GRP*A_STEP_B*2 + GRP*X_STEP_B + GRP*C_STEP_B)  // 17408
#define OFF_A 0
#define OFF_B (GRP * A_STEP_B)             // 8192
#define OFF_X (2 * GRP * A_STEP_B)         // 16384
#define OFF_C (OFF_X + GRP * X_STEP_B)     // 16896
#define MBAR_OFF (STAGES * STAGE_B)        // 208896
#define SMEM_TOTAL (MBAR_OFF + STAGES * 16)

#define NCONS 256                  // consumer threads (8 warps)
#define NTHREADS 288               // + 1 producer warp

// ---- mbarrier / bulk-copy PTX helpers ----------------------------------
#define MBAR_INIT(addr, cnt) \
    asm volatile("mbarrier.init.shared.b64 [%0], %1;" :: "r"(addr), "r"(cnt) : "memory")
#define MBAR_EXPECT_TX(addr, bytes) \
    asm volatile("mbarrier.arrive.expect_tx.shared.b64 _, [%0], %1;" :: "r"(addr), "r"(bytes) : "memory")
#define MBAR_ARRIVE(addr) \
    asm volatile("mbarrier.arrive.shared.b64 _, [%0];" :: "r"(addr) : "memory")
#define MBAR_WAIT_PARITY(addr, ph) do {                                        \
    uint32_t _mb = (addr); uint32_t _p = (ph); uint32_t _done;                 \
    asm volatile("{\n\t.reg .pred p;\n\t"                                      \
        "mbarrier.try_wait.parity.acquire.cta.shared::cta.b64 p, [%1], %2;\n\t"\
        "selp.b32 %0, 1, 0, p;\n\t}"                                           \
        : "=r"(_done) : "r"(_mb), "r"(_p) : "memory");                         \
    if (!_done) {                                                              \
        asm volatile("{\n\t.reg .pred P1;\n\t"                                 \
            "W_%=:\n\t"                                                        \
            "mbarrier.try_wait.parity.acquire.cta.shared::cta.b64 P1, [%0], %1, 0x989680;\n\t" \
            "@P1 bra.uni D_%=;\n\t"                                            \
            "bra.uni W_%=;\n\t"                                                \
            "D_%=:\n\t}"                                                       \
            :: "r"(_mb), "r"(_p) : "memory");                                  \
    }                                                                          \
} while (0)
#define BULK_G2S(dst_smem, src_gmem, bytes, mbar)                              \
    asm volatile("cp.async.bulk.shared::cluster.global.mbarrier::complete_tx::bytes " \
                 "[%0], [%1], %2, [%3];"                                       \
                 :: "r"(dst_smem), "l"(src_gmem), "r"(bytes), "r"(mbar) : "memory")

__global__ void __launch_bounds__(NTHREADS) ssm_scan_tma_kernel(
    const float* __restrict__ A,
    const float* __restrict__ B,
    const float* __restrict__ C,
    const float* __restrict__ x,
    float* __restrict__ y)
{
    extern __shared__ char smem[];
    const uint32_t sbase = (uint32_t)__cvta_generic_to_shared(smem);
    const uint32_t mbase = sbase + MBAR_OFF;

    const int tid = threadIdx.x;
    const int blk = blockIdx.x;            // 0..127
    const int b   = blk >> 6;              // 64 blocks per batch
    const int d0  = (blk & 63) * D_PER_BLK;

    // byte base offsets
    const char* Abase = (const char*)A + (size_t)b * SSM_S * 65536 + (size_t)d0 * 64;
    const char* Bbase = (const char*)B + (size_t)b * SSM_S * 65536 + (size_t)d0 * 64;
    const char* Cbase = (const char*)C + (size_t)b * SSM_S * 64;
    const char* xbase = (const char*)x + (size_t)b * SSM_S * 4096 + (size_t)d0 * 4;

    if (tid == 0) {
        for (int i = 0; i < STAGES; ++i) {
            MBAR_INIT(mbase + i * 16, 1);         // full: 1 arrive (expect_tx)
            MBAR_INIT(mbase + i * 16 + 8, NCONS); // empty: 256 arrivals
        }
    }
    __syncthreads();

    if (tid >= NCONS) {
        // ----------------- producer (warp 8, one thread) -----------------
        if (tid == NCONS) {
            int stage = 0, phase = 1;             // first empty-wait passes
            for (int g = 0; g < NGRP; ++g) {
                const uint32_t fullb  = mbase + stage * 16;
                const uint32_t emptyb = fullb + 8;
                MBAR_WAIT_PARITY(emptyb, phase);
                MBAR_EXPECT_TX(fullb, (uint32_t)STAGE_B);

                const uint32_t sb = sbase + stage * STAGE_B;
                const size_t s0 = (size_t)g * GRP;
                const char* Ag = Abase + s0 * 65536;
                const char* Bg = Bbase + s0 * 65536;
                const char* xg = xbase + s0 * 4096;
                const char* Cg = Cbase + s0 * 64;
#pragma unroll
                for (int i = 0; i < GRP; ++i) {
                    BULK_G2S(sb + OFF_A + i * A_STEP_B, Ag + (size_t)i * 65536,
                             (uint32_t)A_STEP_B, fullb);
                    BULK_G2S(sb + OFF_B + i * A_STEP_B, Bg + (size_t)i * 65536,
                             (uint32_t)A_STEP_B, fullb);
                    BULK_G2S(sb + OFF_X + i * X_STEP_B, xg + (size_t)i * 4096,
                             (uint32_t)X_STEP_B, fullb);
                }
                BULK_G2S(sb + OFF_C, Cg, (uint32_t)(GRP * C_STEP_B), fullb);

                if (++stage == STAGES) { stage = 0; phase ^= 1; }
            }
        }
        return;
    }

    // ------------------------- consumers (warps 0-7) ----------------------
    const int n       = tid & (SSM_N - 1);
    const int d_local = tid >> 4;                  // 0..15
    const bool writer = (n == 0);
    float* yp = y + ((size_t)b * SSM_S) * SSM_D + d0 + d_local;

    const float* smf = (const float*)smem;
    float h = 0.0f;
    int stage = 0, phase = 0;

    for (int g = 0; g < NGRP; ++g) {
        const uint32_t fullb  = mbase + stage * 16;
        const uint32_t emptyb = fullb + 8;
        MBAR_WAIT_PARITY(fullb, phase);

        const int sw = stage * (STAGE_B / 4);      // stage base in floats
        // Load the whole group's operands first (ILP over 8 steps).
        float av[GRP], bv[GRP], xv[GRP], cv[GRP];
#pragma unroll
        for (int i = 0; i < GRP; ++i) {
            av[i] = smf[sw + (OFF_A / 4) + i * 256 + d_local * 16 + n];
            bv[i] = smf[sw + (OFF_B / 4) + i * 256 + d_local * 16 + n];
            xv[i] = smf[sw + (OFF_X / 4) + i * 16 + d_local];
            cv[i] = smf[sw + (OFF_C / 4) + i * 16 + n];
        }
#pragma unroll
        for (int i = 0; i < GRP; ++i) {
            h = fmaf(av[i], h, bv[i] * xv[i]);
            float p = cv[i] * h;
            p += __shfl_xor_sync(0xFFFFFFFFu, p, 8);
            p += __shfl_xor_sync(0xFFFFFFFFu, p, 4);
            p += __shfl_xor_sync(0xFFFFFFFFu, p, 2);
            p += __shfl_xor_sync(0xFFFFFFFFu, p, 1);
            if (writer) yp[(g * GRP + i) * SSM_D] = p;
        }

        MBAR_ARRIVE(emptyb);
        if (++stage == STAGES) { stage = 0; phase ^= 1; }
    }
}

extern "C" void kernel_launch(void* const* d_in, const int* in_sizes, int n_in,
                              void* d_out, int out_size)
{
    const float* A = (const float*)d_in[0];
    const float* B = (const float*)d_in[1];
    const float* C = (const float*)d_in[2];
    const float* x = (const float*)d_in[3];
    float*       y = (float*)d_out;

    cudaFuncSetAttribute(ssm_scan_tma_kernel,
                         cudaFuncAttributeMaxDynamicSharedMemorySize, SMEM_TOTAL);

    const int grid = SSM_B * (SSM_D / D_PER_BLK);   // 128 blocks
    ssm_scan_tma_kernel<<<grid, NTHREADS, SMEM_TOTAL>>>(A, B, C, x, y);
}

// round 15
// speedup vs baseline: 1.7206x; 1.7206x over previous
#include <cuda_runtime.h>
#include <cstdint>

// SSM scan: h_t = A_t*h_{t-1} + B_t*x_t ; y_t[d] = sum_n C_t[n]*h_t[d,n]
// A,B [2,2048,1024,16] f32; C [2,2048,16]; x [2,2048,1024]; y [2,2048,1024].
//
// R11: symmetric cp.async (LDGSTS) pipeline. R10's warp-specialized TMA ring
// serialized on the single-producer bulk-copy issue (25 copies/group x ~46cyc
// ~= the measured 1400cyc group period) and on mbarrier arrive/wait overhead.
// Here ALL 256 threads issue 16B cp.async.cg copies (parallel issue, ~4
// warp-instr/warp/group), and sync is one __syncthreads + wait_group per
// group. Ring: 12 stages x 8 steps x 17408B ~= 190KB/block in flight,
// x128 blocks ~= 24MB chip-wide -> DRAM-bound.

#define SSM_S 2048
#define SSM_D 1024
#define SSM_N 16
#define SSM_B 2

#define D_PER_BLK 16
#define GRP 8                       // steps per pipeline stage
#define NGRP (SSM_S / GRP)          // 256 groups
#define STAGES 12

#define A_STEP_B 1024               // 16 d * 16 n * 4B
#define STAGE_B (GRP*A_STEP_B*2 + GRP*64 + GRP*64)   // 17408
#define OFF_A 0
#define OFF_B (GRP * A_STEP_B)              // 8192
#define OFF_X (2 * GRP * A_STEP_B)          // 16384
#define OFF_C (OFF_X + GRP * 64)            // 16896
#define SMEM_TOTAL (STAGES * STAGE_B)       // 208896

#define NTHREADS 256

#define CP16(dst, src) \
    asm volatile("cp.async.cg.shared.global [%0], [%1], 16;" \
                 :: "r"(dst), "l"(src) : "memory")
#define CP_COMMIT() asm volatile("cp.async.commit_group;" ::: "memory")
#define CP_WAIT(n)  asm volatile("cp.async.wait_group %0;" :: "n"(n) : "memory")

__global__ void __launch_bounds__(NTHREADS) ssm_cpasync_kernel(
    const float* __restrict__ A,
    const float* __restrict__ B,
    const float* __restrict__ C,
    const float* __restrict__ x,
    float* __restrict__ y)
{
    extern __shared__ char smem[];
    const uint32_t sbase = (uint32_t)__cvta_generic_to_shared(smem);

    const int tid = threadIdx.x;
    const int blk = blockIdx.x;            // 0..127
    const int b   = blk >> 6;
    const int d0  = (blk & 63) * D_PER_BLK;

    const char* Abase = (const char*)A + (size_t)b * SSM_S * 65536 + (size_t)d0 * 64;
    const char* Bbase = (const char*)B + (size_t)b * SSM_S * 65536 + (size_t)d0 * 64;
    const char* Cbase = (const char*)C + (size_t)b * SSM_S * 64;
    const char* xbase = (const char*)x + (size_t)b * SSM_S * 4096 + (size_t)d0 * 4;

    // ---- per-thread copy assignments for one group ----------------------
    // A: 512 x 16B chunks -> threads tid and tid+256
    // B: same
    // x: 32 chunks (tid < 32) ; C: 32 chunks (32 <= tid < 64)
    const int kx = tid;            // x chunk id if tid<32
    const int kc = tid - 32;       // C chunk id if 32<=tid<64

#define ISSUE_GROUP(g, stage)                                                  \
    {                                                                          \
        const uint32_t sb = sbase + (stage) * STAGE_B;                         \
        const size_t s0 = (size_t)(g) * GRP;                                   \
        _Pragma("unroll")                                                      \
        for (int r = 0; r < 2; ++r) {                                          \
            const int k = tid + r * 256;                                       \
            const int i = k >> 6;                                              \
            const int off = (k & 63) * 16;                                     \
            CP16(sb + OFF_A + k * 16, Abase + (s0 + i) * 65536 + off);         \
            CP16(sb + OFF_B + k * 16, Bbase + (s0 + i) * 65536 + off);         \
        }                                                                      \
        if (tid < 32) {                                                        \
            const int i = kx >> 2;                                             \
            CP16(sb + OFF_X + kx * 16,                                         \
                 xbase + (s0 + i) * 4096 + (kx & 3) * 16);                     \
        } else if (tid < 64) {                                                 \
            CP16(sb + OFF_C + kc * 16, Cbase + s0 * 64 + kc * 16);             \
        }                                                                      \
        CP_COMMIT();                                                           \
    }

    // Prologue: fill STAGES-1 groups.
#pragma unroll
    for (int g = 0; g < STAGES - 1; ++g)
        ISSUE_GROUP(g, g)

    const int n       = tid & (SSM_N - 1);
    const int d_local = tid >> 4;
    const bool writer = (n == 0);
    float* yp = y + ((size_t)b * SSM_S) * SSM_D + d0 + d_local;

    const float* smf = (const float*)smem;
    float h = 0.0f;
    int stage = 0;

    for (int g = 0; g < NGRP; ++g) {
        // Group g complete when <= STAGES-2 commit-groups pending.
        CP_WAIT(STAGES - 2);
        __syncthreads();

        const int sw = stage * (STAGE_B / 4);
        float av[GRP], bv[GRP], xv[GRP], cv[GRP];
#pragma unroll
        for (int i = 0; i < GRP; ++i) {
            av[i] = smf[sw + (OFF_A / 4) + i * 256 + d_local * 16 + n];
            bv[i] = smf[sw + (OFF_B / 4) + i * 256 + d_local * 16 + n];
            xv[i] = smf[sw + (OFF_X / 4) + i * 16 + d_local];
            cv[i] = smf[sw + (OFF_C / 4) + i * 16 + n];
        }
#pragma unroll
        for (int i = 0; i < GRP; ++i) {
            h = fmaf(av[i], h, bv[i] * xv[i]);
            float p = cv[i] * h;
            p += __shfl_xor_sync(0xFFFFFFFFu, p, 8);
            p += __shfl_xor_sync(0xFFFFFFFFu, p, 4);
            p += __shfl_xor_sync(0xFFFFFFFFu, p, 2);
            p += __shfl_xor_sync(0xFFFFFFFFu, p, 1);
            if (writer) yp[(g * GRP + i) * SSM_D] = p;
        }

        // Refill the stage freed last iteration with group g+STAGES-1.
        const int gNext = g + STAGES - 1;
        if (gNext < NGRP) {
            const int stNext = (stage + STAGES - 1) % STAGES;
            ISSUE_GROUP(gNext, stNext)
        } else {
            CP_COMMIT();       // keep commit-count invariant (empty group)
        }

        if (++stage == STAGES) stage = 0;
    }
#undef ISSUE_GROUP
}

extern "C" void kernel_launch(void* const* d_in, const int* in_sizes, int n_in,
                              void* d_out, int out_size)
{
    const float* A = (const float*)d_in[0];
    const float* B = (const float*)d_in[1];
    const float* C = (const float*)d_in[2];
    const float* x = (const float*)d_in[3];
    float*       y = (float*)d_out;

    cudaFuncSetAttribute(ssm_cpasync_kernel,
                         cudaFuncAttributeMaxDynamicSharedMemorySize, SMEM_TOTAL);

    const int grid = SSM_B * (SSM_D / D_PER_BLK);   // 128 blocks
    ssm_cpasync_kernel<<<grid, NTHREADS, SMEM_TOTAL>>>(A, B, C, x, y);
}